// round 5
// baseline (speedup 1.0000x reference)
#include <cuda_runtime.h>
#include <cstdint>

#define B_    16
#define FIN_  16
#define FOUT_ 16
#define H_    384
#define W_    384
#define LAT_  512
#define NMIX_ 8
#define HW_   (H_ * W_)          // 147456
#define PLANE4_ (HW_ / 4)        // 36864 float4 groups per channel plane
#define GX_   36                 // blocks along pixel dim
#define ITERS_ 4                 // tiles per block: 36*4*256 = 36864

__device__ __forceinline__ unsigned long long pack2(float v) {
    unsigned int u = __float_as_uint(v);
    return ((unsigned long long)u << 32) | (unsigned long long)u;
}

__device__ __forceinline__ unsigned long long ffma2(unsigned long long a,
                                                    unsigned long long b,
                                                    unsigned long long c) {
    unsigned long long d;
    asm("fma.rn.f32x2 %0, %1, %2, %3;" : "=l"(d) : "l"(a), "l"(b), "l"(c));
    return d;
}

// ---------------------------------------------------------------------------
// Fused, phase-1-amortized kernel.
//   Phase 1 (once per block, 576 blocks): warp m computes
//     mix[b][m] = dot(lat[b], w_dyn[m]) + b_dyn[m]; then 256 threads build
//     the per-sample 16x16 kernel + bias in smem, packed {k,k} for f32x2.
//   Phase 2 (x4 iterations): float4 streaming tile.
//     Per thread/iter: 16 LDG.128, 128 LDS.128 (k pairs), 512 ffma2, 16 STG.128.
// ---------------------------------------------------------------------------
__global__ void __launch_bounds__(256, 2)
mixconv_fused(const float* __restrict__ x,
              const float* __restrict__ lat,
              const float* __restrict__ kernel_mix,
              const float* __restrict__ bias_mix,
              const float* __restrict__ w_dyn,
              const float* __restrict__ b_dyn,
              float* __restrict__ out) {
    __shared__ float s_mix[NMIX_];
    __shared__ __align__(16) unsigned long long sk[FOUT_ * FIN_]; // packed {k,k}
    __shared__ unsigned long long sb[FOUT_];

    const int b    = blockIdx.y;
    const int t    = threadIdx.x;
    const int w    = t >> 5;      // warp id 0..7 == mixture index
    const int lane = t & 31;

    // ---- Phase 1a: mix[b][w] via warp-parallel dot product -------------
    {
        const float* __restrict__ lp = lat + b * LAT_;
        const float* __restrict__ wp = w_dyn + w * LAT_;
        float s = 0.f;
        #pragma unroll
        for (int j = 0; j < LAT_ / 32; ++j)
            s = fmaf(__ldg(lp + lane + 32 * j), __ldg(wp + lane + 32 * j), s);
        #pragma unroll
        for (int off = 16; off > 0; off >>= 1)
            s += __shfl_xor_sync(0xffffffffu, s, off);
        if (lane == 0) s_mix[w] = s + __ldg(b_dyn + w);
    }
    __syncthreads();

    // ---- Phase 1b: per-sample kernel + bias into smem ------------------
    {
        float s = 0.f;
        #pragma unroll
        for (int m = 0; m < NMIX_; ++m)
            s = fmaf(s_mix[m], __ldg(kernel_mix + m * (FOUT_ * FIN_) + t), s);
        sk[t] = pack2(s);
        if (t < FOUT_) {
            float sv = 0.f;
            #pragma unroll
            for (int m = 0; m < NMIX_; ++m)
                sv = fmaf(s_mix[m], __ldg(bias_mix + m * FOUT_ + t), sv);
            sb[t] = pack2(sv);
        }
    }
    __syncthreads();

    // ---- Phase 2: 4 float4 streaming tiles ------------------------------
    const ulonglong2* __restrict__ xp =
        (const ulonglong2*)(x + (size_t)b * FIN_ * HW_);
    ulonglong2* __restrict__ op =
        (ulonglong2*)(out + (size_t)b * FOUT_ * HW_);
    const ulonglong2* __restrict__ sk2 = (const ulonglong2*)sk;

    #pragma unroll 1
    for (int it = 0; it < ITERS_; ++it) {
        const int p = (blockIdx.x + GX_ * it) * 256 + t;   // float4 group index

        unsigned long long in_lo[FIN_], in_hi[FIN_];
        #pragma unroll
        for (int i = 0; i < FIN_; ++i) {
            ulonglong2 v = xp[(size_t)i * PLANE4_ + p];
            in_lo[i] = v.x;
            in_hi[i] = v.y;
        }

        #pragma unroll
        for (int o = 0; o < FOUT_; ++o) {
            unsigned long long alo = sb[o];
            unsigned long long ahi = alo;
            #pragma unroll
            for (int j = 0; j < FIN_ / 2; ++j) {
                ulonglong2 kk = sk2[o * (FIN_ / 2) + j];   // two packed {k,k}
                alo = ffma2(kk.x, in_lo[2 * j],     alo);
                ahi = ffma2(kk.x, in_hi[2 * j],     ahi);
                alo = ffma2(kk.y, in_lo[2 * j + 1], alo);
                ahi = ffma2(kk.y, in_hi[2 * j + 1], ahi);
            }
            ulonglong2 r;
            r.x = alo;
            r.y = ahi;
            op[(size_t)o * PLANE4_ + p] = r;
        }
    }
}

// ---------------------------------------------------------------------------
extern "C" void kernel_launch(void* const* d_in, const int* in_sizes, int n_in,
                              void* d_out, int out_size) {
    const float* x          = (const float*)d_in[0];  // [16,16,384,384]
    const float* lat        = (const float*)d_in[1];  // [16,512]
    const float* kernel_mix = (const float*)d_in[2];  // [8,16,16]
    const float* bias_mix   = (const float*)d_in[3];  // [8,16]
    const float* w_dyn      = (const float*)d_in[4];  // [8,512]
    const float* b_dyn      = (const float*)d_in[5];  // [8]
    float* out = (float*)d_out;

    dim3 grid(GX_, B_);   // (36, 16) = 576 blocks, 4 tiles each
    mixconv_fused<<<grid, 256>>>(x, lat, kernel_mix, bias_mix, w_dyn, b_dyn, out);
}

// round 6
// speedup vs baseline: 6.5595x; 6.5595x over previous
#include <cuda_runtime.h>
#include <cstdint>

#define B_    16
#define FIN_  16
#define FOUT_ 16
#define H_    384
#define W_    384
#define LAT_  512
#define NMIX_ 8
#define HW_   (H_ * W_)        // 147456
#define PLANE4_ (HW_ / 4)      // 36864 float4 groups per channel plane

// Scratch (no-allocation rule): per-sample kernel packed as {k,k} f32x2 words.
__device__ unsigned long long g_k2[B_ * FOUT_ * FIN_];   // 4096 * 8B = 32 KB
__device__ unsigned long long g_b2[B_ * FOUT_];          // 256 * 8B

__device__ __forceinline__ unsigned long long pack2(float v) {
    unsigned int u = __float_as_uint(v);
    return ((unsigned long long)u << 32) | (unsigned long long)u;
}

__device__ __forceinline__ unsigned long long ffma2(unsigned long long a,
                                                    unsigned long long b,
                                                    unsigned long long c) {
    unsigned long long d;
    asm("fma.rn.f32x2 %0, %1, %2, %3;" : "=l"(d) : "l"(a), "l"(b), "l"(c));
    return d;
}

// ---------------------------------------------------------------------------
// Kernel A (fast prep): one block per sample b, 256 threads.
//   Warp m: mix[b][m] = dot(lat[b], w_dyn[m]) + b_dyn[m]  (warp-parallel+shfl)
//   Then 256 threads build K[b] (16x16) and bias[b], packed {k,k}.
//   ~2us total, vs ~28us for the serial-dot version.
// ---------------------------------------------------------------------------
__global__ void mixconv_prep(const float* __restrict__ lat,
                             const float* __restrict__ kernel_mix,
                             const float* __restrict__ bias_mix,
                             const float* __restrict__ w_dyn,
                             const float* __restrict__ b_dyn) {
    __shared__ float s_mix[NMIX_];
    const int b    = blockIdx.x;
    const int t    = threadIdx.x;
    const int w    = t >> 5;      // warp id 0..7 == mixture index
    const int lane = t & 31;

    {
        const float* __restrict__ lp = lat + b * LAT_;
        const float* __restrict__ wp = w_dyn + w * LAT_;
        float s = 0.f;
        #pragma unroll
        for (int j = 0; j < LAT_ / 32; ++j)
            s = fmaf(lp[lane + 32 * j], wp[lane + 32 * j], s);
        #pragma unroll
        for (int off = 16; off > 0; off >>= 1)
            s += __shfl_xor_sync(0xffffffffu, s, off);
        if (lane == 0) s_mix[w] = s + b_dyn[w];
    }
    __syncthreads();

    {
        float s = 0.f;
        #pragma unroll
        for (int m = 0; m < NMIX_; ++m)
            s = fmaf(s_mix[m], kernel_mix[m * (FOUT_ * FIN_) + t], s);
        g_k2[b * (FOUT_ * FIN_) + t] = pack2(s);
        if (t < FOUT_) {
            float sv = 0.f;
            #pragma unroll
            for (int m = 0; m < NMIX_; ++m)
                sv = fmaf(s_mix[m], bias_mix[m * FOUT_ + t], sv);
            g_b2[b * FOUT_ + t] = pack2(sv);
        }
    }
}

// ---------------------------------------------------------------------------
// Kernel B: streaming conv, identical to the proven 45.4us R2 kernel.
// grid = (144, 16), block = 256. One float4 group per thread:
// 16 LDG.128 in, 512 fma.f32x2, 16 STG.128 out. Straight-line body -> no spill.
// ---------------------------------------------------------------------------
__global__ void __launch_bounds__(256, 2)
mixconv_main(const float* __restrict__ x, float* __restrict__ out) {
    __shared__ unsigned long long sk[FOUT_ * FIN_];  // packed {k,k}
    __shared__ unsigned long long sb[FOUT_];

    const int b = blockIdx.y;
    const int t = threadIdx.x;

    sk[t] = g_k2[b * (FOUT_ * FIN_) + t];           // 256 threads, 256 entries
    if (t < FOUT_) sb[t] = g_b2[b * FOUT_ + t];
    __syncthreads();

    const int p = blockIdx.x * 256 + t;             // float4 group in plane

    const ulonglong2* __restrict__ xp =
        (const ulonglong2*)(x + (size_t)b * FIN_ * HW_);
    ulonglong2* __restrict__ op =
        (ulonglong2*)(out + (size_t)b * FOUT_ * HW_);

    unsigned long long in_lo[FIN_], in_hi[FIN_];
    #pragma unroll
    for (int i = 0; i < FIN_; ++i) {
        ulonglong2 v = xp[(size_t)i * PLANE4_ + p];
        in_lo[i] = v.x;
        in_hi[i] = v.y;
    }

    #pragma unroll
    for (int o = 0; o < FOUT_; ++o) {
        unsigned long long alo = sb[o];
        unsigned long long ahi = alo;
        #pragma unroll
        for (int i = 0; i < FIN_; ++i) {
            unsigned long long k = sk[o * FIN_ + i];   // warp-uniform broadcast LDS.64
            alo = ffma2(k, in_lo[i], alo);
            ahi = ffma2(k, in_hi[i], ahi);
        }
        ulonglong2 r;
        r.x = alo;
        r.y = ahi;
        op[(size_t)o * PLANE4_ + p] = r;
    }
}

// ---------------------------------------------------------------------------
extern "C" void kernel_launch(void* const* d_in, const int* in_sizes, int n_in,
                              void* d_out, int out_size) {
    const float* x          = (const float*)d_in[0];  // [16,16,384,384]
    const float* lat        = (const float*)d_in[1];  // [16,512]
    const float* kernel_mix = (const float*)d_in[2];  // [8,16,16]
    const float* bias_mix   = (const float*)d_in[3];  // [8,16]
    const float* w_dyn      = (const float*)d_in[4];  // [8,512]
    const float* b_dyn      = (const float*)d_in[5];  // [8]
    float* out = (float*)d_out;

    mixconv_prep<<<B_, 256>>>(lat, kernel_mix, bias_mix, w_dyn, b_dyn);

    dim3 grid(PLANE4_ / 256, B_);   // (144, 16) = 2304 blocks
    mixconv_main<<<grid, 256>>>(x, out);
}

// round 7
// speedup vs baseline: 6.5634x; 1.0006x over previous
#include <cuda_runtime.h>
#include <cstdint>

#define B_    16
#define FIN_  16
#define FOUT_ 16
#define H_    384
#define W_    384
#define LAT_  512
#define NMIX_ 8
#define HW_   (H_ * W_)        // 147456
#define PLANE4_ (HW_ / 4)      // 36864 float4 groups per channel plane

__device__ __forceinline__ unsigned long long pack2(float v) {
    unsigned int u = __float_as_uint(v);
    return ((unsigned long long)u << 32) | (unsigned long long)u;
}

__device__ __forceinline__ unsigned long long ffma2(unsigned long long a,
                                                    unsigned long long b,
                                                    unsigned long long c) {
    unsigned long long d;
    asm("fma.rn.f32x2 %0, %1, %2, %3;" : "=l"(d) : "l"(a), "l"(b), "l"(c));
    return d;
}

// ---------------------------------------------------------------------------
// Single fused kernel, float4 body (the proven 45.4us shape), NO outer loop.
//   Phase 1 (per block, ~1.5k cyc, L2-resident data, overlaps partner CTA's
//   streaming): warp m computes mix[b][m] = dot(lat[b], w_dyn[m]) + b_dyn[m];
//   then 256 threads build the 16x16 per-sample kernel + bias in smem,
//   packed {k,k} for fma.rn.f32x2. All phase-1 registers die before phase 2.
//   Phase 2: one float4 pixel group per thread: 16 LDG.128 in, 512 ffma2,
//   16 STG.128 out. Straight-line body -> fits in 128 regs, no spill.
// ---------------------------------------------------------------------------
__global__ void __launch_bounds__(256, 2)
mixconv_fused(const float* __restrict__ x,
              const float* __restrict__ lat,
              const float* __restrict__ kernel_mix,
              const float* __restrict__ bias_mix,
              const float* __restrict__ w_dyn,
              const float* __restrict__ b_dyn,
              float* __restrict__ out) {
    __shared__ float s_mix[NMIX_];
    __shared__ unsigned long long sk[FOUT_ * FIN_];  // packed {k,k}
    __shared__ unsigned long long sb[FOUT_];

    const int b    = blockIdx.y;
    const int t    = threadIdx.x;
    const int w    = t >> 5;      // warp id 0..7 == mixture index
    const int lane = t & 31;

    // ---- Phase 1a: mix[b][w] via warp-parallel dot product -------------
    {
        const float* __restrict__ lp = lat + b * LAT_;
        const float* __restrict__ wp = w_dyn + w * LAT_;
        float s = 0.f;
        #pragma unroll
        for (int j = 0; j < LAT_ / 32; ++j)
            s = fmaf(__ldg(lp + lane + 32 * j), __ldg(wp + lane + 32 * j), s);
        #pragma unroll
        for (int off = 16; off > 0; off >>= 1)
            s += __shfl_xor_sync(0xffffffffu, s, off);
        if (lane == 0) s_mix[w] = s + __ldg(b_dyn + w);
    }
    __syncthreads();

    // ---- Phase 1b: per-sample kernel + bias into smem ------------------
    {
        float s = 0.f;
        #pragma unroll
        for (int m = 0; m < NMIX_; ++m)
            s = fmaf(s_mix[m], __ldg(kernel_mix + m * (FOUT_ * FIN_) + t), s);
        sk[t] = pack2(s);
        if (t < FOUT_) {
            float sv = 0.f;
            #pragma unroll
            for (int m = 0; m < NMIX_; ++m)
                sv = fmaf(s_mix[m], __ldg(bias_mix + m * FOUT_ + t), sv);
            sb[t] = pack2(sv);
        }
    }
    __syncthreads();

    // ---- Phase 2: one float4 streaming tile (R2-identical body) --------
    const int p = blockIdx.x * 256 + t;             // float4 group in plane

    const ulonglong2* __restrict__ xp =
        (const ulonglong2*)(x + (size_t)b * FIN_ * HW_);
    ulonglong2* __restrict__ op =
        (ulonglong2*)(out + (size_t)b * FOUT_ * HW_);

    unsigned long long in_lo[FIN_], in_hi[FIN_];
    #pragma unroll
    for (int i = 0; i < FIN_; ++i) {
        ulonglong2 v = xp[(size_t)i * PLANE4_ + p];
        in_lo[i] = v.x;
        in_hi[i] = v.y;
    }

    #pragma unroll
    for (int o = 0; o < FOUT_; ++o) {
        unsigned long long alo = sb[o];
        unsigned long long ahi = alo;
        #pragma unroll
        for (int i = 0; i < FIN_; ++i) {
            unsigned long long k = sk[o * FIN_ + i];   // warp-uniform broadcast LDS.64
            alo = ffma2(k, in_lo[i], alo);
            ahi = ffma2(k, in_hi[i], ahi);
        }
        ulonglong2 r;
        r.x = alo;
        r.y = ahi;
        op[(size_t)o * PLANE4_ + p] = r;
    }
}

// ---------------------------------------------------------------------------
extern "C" void kernel_launch(void* const* d_in, const int* in_sizes, int n_in,
                              void* d_out, int out_size) {
    const float* x          = (const float*)d_in[0];  // [16,16,384,384]
    const float* lat        = (const float*)d_in[1];  // [16,512]
    const float* kernel_mix = (const float*)d_in[2];  // [8,16,16]
    const float* bias_mix   = (const float*)d_in[3];  // [8,16]
    const float* w_dyn      = (const float*)d_in[4];  // [8,512]
    const float* b_dyn      = (const float*)d_in[5];  // [8]
    float* out = (float*)d_out;

    dim3 grid(PLANE4_ / 256, B_);   // (144, 16) = 2304 blocks, one tile each
    mixconv_fused<<<grid, 256>>>(x, lat, kernel_mix, bias_mix, w_dyn, b_dyn, out);
}